// round 9
// baseline (speedup 1.0000x reference)
#include <cuda_runtime.h>
#include <cuda_fp16.h>
#include <mma.h>
#include <math.h>

using namespace nvcuda;

#define NN 100000
#define EE 800000
#define H  32
#define NL 4
#define FULL 0xffffffffu
#define SCAN_N   (NN + 1)
#define SCAN_NB  ((SCAN_N + 1023) / 1024)

// ---------------- scratch ---------------------------------------------------------
__device__ float  g_h[NN*H];
__device__ float  g_hnew[NN*H];
__device__ float  g_Ah[NN*H];
__device__ float  g_Bh[NN*H];
__device__ float  g_Uh[NN*H];
__device__ float  g_Vh[NN*H];
__device__ __half g_e[EE*H];       // e_l (dst-sorted)
__device__ __half g_ce[EE*H];      // Ce (fp16 storage, fp32 accum); enew reconstructed
// stats slots: per layer l: [l*128 + 0:64) h sum/sq, [l*128+64:128) e sum/sq
__device__ float  g_stats[NL*128];
__device__ int    g_hist[SCAN_NB*1024];   // zero at load; scan re-zeros (leave-clean)
__device__ int    g_rowptr[NN+1];
__device__ int    g_cursor[NN];
__device__ int    g_bsum[SCAN_NB];
__device__ int    g_sync;
__device__ int    g_ssrc[EE];
__device__ int    g_sdst[EE];
__device__ int    g_oid[EE];

// ---------------- CSR build -------------------------------------------------------
__global__ void hist_kernel(const int* __restrict__ dst, int ne)
{
    if (blockIdx.x == 0) {
        if (threadIdx.x == 0) g_sync = 0;
        for (int i = threadIdx.x; i < NL*128; i += blockDim.x) g_stats[i] = 0.f;
    }
    for (int i = blockIdx.x * blockDim.x + threadIdx.x; i < ne;
         i += gridDim.x * blockDim.x)
        atomicAdd(&g_hist[dst[i]], 1);
}

// single-kernel scan: all SCAN_NB (=98) blocks resident; aggregate + spin barrier.
__global__ void scan_fused()
{
    __shared__ int sm[1024];
    int b = blockIdx.x, t = threadIdx.x;
    int idx = b*1024 + t;
    int v = (idx < SCAN_N) ? g_hist[idx] : 0;
    if (idx < SCAN_N) g_hist[idx] = 0;        // leave clean for next graph replay
    sm[t] = v;
    __syncthreads();
    for (int off = 1; off < 1024; off <<= 1) {
        int u = (t >= off) ? sm[t - off] : 0;
        __syncthreads();
        sm[t] += u;
        __syncthreads();
    }
    if (t == 1023) {
        g_bsum[b] = sm[1023];
        __threadfence();
        atomicAdd(&g_sync, 1);
    }
    if (t == 0) {
        while (atomicAdd(&g_sync, 0) < (int)gridDim.x) __nanosleep(64);
    }
    __syncthreads();
    int pre = 0;
    for (int i = 0; i < b; i++) pre += g_bsum[i];
    int excl = pre + sm[t] - v;
    if (idx < SCAN_N) {
        g_rowptr[idx] = excl;
        if (idx < NN) g_cursor[idx] = excl;
    }
}

__global__ void scatter_kernel(const int* __restrict__ src, const int* __restrict__ dst,
                               int ne)
{
    for (int i = blockIdx.x * blockDim.x + threadIdx.x; i < ne;
         i += gridDim.x * blockDim.x) {
        int d = dst[i];
        int pos = atomicAdd(&g_cursor[d], 1);
        g_ssrc[pos] = src[i];
        g_sdst[pos] = d;
        g_oid[pos]  = i;
    }
}

// ------- gemm4: weights in REGISTERS (zero LDS); grid-stride over rows -----------
__global__ void __launch_bounds__(128)
gemm4_fused(const float* __restrict__ Aw, const float* __restrict__ Ab,
            const float* __restrict__ Bw, const float* __restrict__ Bb,
            const float* __restrict__ Uw, const float* __restrict__ Ub,
            const float* __restrict__ Vw, const float* __restrict__ Vb,
            const float* __restrict__ bng, const float* __restrict__ bnb,
            const float* __restrict__ x,
            const float* __restrict__ pw, const float* __restrict__ pb,
            int statSlot, int mode /*0=proj,1=update*/, int n)
{
    int lane = threadIdx.x & 31;
    float wA[32], wB[32], wU[32], wV[32];
    #pragma unroll
    for (int k = 0; k < 32; k++) {
        wA[k] = Aw[k*H + lane];
        wB[k] = Bw[k*H + lane];
        wU[k] = Uw[k*H + lane];
        wV[k] = Vw[k*H + lane];
    }
    float bA = Ab[lane], bB = Bb[lane], bU = Ub[lane], bV = Vb[lane];

    float mn = 0.f, sc = 0.f, bt = 0.f, pwl = 0.f, pbl = 0.f;
    if (mode == 1) {
        float inv = 1.0f / (float)n;
        float s1 = g_stats[statSlot*128 + lane];
        float s2 = g_stats[statSlot*128 + 32 + lane];
        mn = s1 * inv;
        float var = s2 * inv - mn * mn;
        sc = rsqrtf(var + 1e-5f) * bng[lane];
        bt = bnb[lane];
    } else {
        pwl = pw[lane]; pbl = pb[lane];
    }

    int warp0  = blockIdx.x * (blockDim.x >> 5) + (threadIdx.x >> 5);
    int stride = gridDim.x * (blockDim.x >> 5);
    for (int row = warp0; row < n; row += stride) {
        float hv;
        if (mode == 0) {
            hv = x[row] * pwl + pbl;
            g_h[row*H + lane] = hv;
        } else {
            hv = g_h[row*H + lane];
            float v = (g_hnew[row*H + lane] - mn) * sc + bt;
            hv += fmaxf(v, 0.f);
            g_h[row*H + lane] = hv;
        }
        float a = bA, b = bB, u = bU, v = bV;
        #pragma unroll
        for (int k = 0; k < 32; k++) {
            float hk = __shfl_sync(FULL, hv, k);
            a += hk * wA[k];
            b += hk * wB[k];
            u += hk * wU[k];
            v += hk * wV[k];
        }
        g_Ah[row*H + lane] = a;
        g_Bh[row*H + lane] = b;
        g_Uh[row*H + lane] = u;
        g_Vh[row*H + lane] = v;
    }
}

// ---- tensor-core edge GEMM -> fp16 ce. 2 MMA-tiles (32 rows) per warp per iter.
// eMode 1: project e from input (layer 0).
// eMode 2: reconstruct enew_{l-1} = Ah[d]+Bh[s]+ce_prev, apply e += relu(BN(enew));
//          write e back iff writeE. Must run BEFORE next layer's gemm4.
__global__ void __launch_bounds__(128)
ce_mma(const float* __restrict__ W, const float* __restrict__ bias,
       const float* __restrict__ bng, const float* __restrict__ bnb,
       const float* __restrict__ ein,
       const float* __restrict__ ew, const float* __restrict__ eb,
       int prevSlot, int eMode, int writeE, int ne, float inv_ne)
{
    __shared__ __half sWhi[32*32], sWlo[32*32];
    __shared__ __half sE[4][32*32];     // 32 rows per warp
    __shared__ float  sC[4][32*32];
    __shared__ float  sBias[32], sMn[32], sSc[32], sBt[32], sEw[32], sEb[32];

    int tid = threadIdx.x;
    for (int i = tid; i < 1024; i += 128) {
        float w = W[i];
        __half hi = __float2half_rn(w);
        sWhi[i] = hi;
        sWlo[i] = __float2half_rn(w - __half2float(hi));
    }
    if (tid < 32) {
        sBias[tid] = bias ? bias[tid] : 0.f;
        sMn[tid] = 0.f; sSc[tid] = 0.f; sBt[tid] = 0.f;
        sEw[tid] = 0.f; sEb[tid] = 0.f;
        if (eMode == 2) {
            float s1 = g_stats[prevSlot*128 + 64 + tid];
            float s2 = g_stats[prevSlot*128 + 96 + tid];
            float mean = s1 * inv_ne;
            float var  = s2 * inv_ne - mean * mean;
            sMn[tid] = mean;
            sSc[tid] = rsqrtf(var + 1e-5f) * bng[tid];
            sBt[tid] = bnb[tid];
        } else if (eMode == 1) {
            sEw[tid] = ew[tid]; sEb[tid] = eb[tid];
        }
    }
    __syncthreads();

    int warp = tid >> 5, lane = tid & 31;

    wmma::fragment<wmma::matrix_b, 16,16,16, __half, wmma::row_major> bh[2][2], bl[2][2];
    #pragma unroll
    for (int kk = 0; kk < 2; kk++)
        #pragma unroll
        for (int nn = 0; nn < 2; nn++) {
            wmma::load_matrix_sync(bh[kk][nn], sWhi + kk*16*32 + nn*16, 32);
            wmma::load_matrix_sync(bl[kk][nn], sWlo + kk*16*32 + nn*16, 32);
        }

    __half2* e2  = (__half2*)g_e;
    __half2* ce2 = (__half2*)g_ce;
    int nt2 = (ne + 127) >> 7;          // 128 rows per block iteration

    for (int p = blockIdx.x; p < nt2; p += gridDim.x) {
        int rbase = p*128 + warp*32;    // this warp's 32 rows
        __half2* stage = (__half2*)sE[warp];
        // stage 32 rows x 16 half2 = 512 slots; gathers for both tiles in flight
        #pragma unroll
        for (int i = 0; i < 16; i++) {
            int idx = i*32 + lane;
            int row = rbase + (idx >> 4);
            int ch  = idx & 15;
            if (row < ne) {
                size_t g = (size_t)row*16 + ch;
                if (eMode == 1) {
                    float xin = ein[g_oid[row]];
                    int c = ch*2;
                    __half2 nv = __floats2half2_rn(xin*sEw[c] + sEb[c],
                                                   xin*sEw[c+1] + sEb[c+1]);
                    e2[g] = nv;
                    stage[idx] = nv;
                } else {
                    int s = g_ssrc[row], d = g_sdst[row];
                    int c = ch*2;
                    float2 ah  = *(const float2*)(g_Ah + d*H + c);
                    float2 bhv = *(const float2*)(g_Bh + s*H + c);
                    float2 ce  = __half22float2(ce2[g]);
                    float enx = ah.x + bhv.x + ce.x;
                    float eny = ah.y + bhv.y + ce.y;
                    float2 f = __half22float2(e2[g]);
                    f.x += fmaxf((enx - sMn[c])   * sSc[c]   + sBt[c],   0.f);
                    f.y += fmaxf((eny - sMn[c+1]) * sSc[c+1] + sBt[c+1], 0.f);
                    __half2 nv = __floats2half2_rn(f.x, f.y);
                    if (writeE) e2[g] = nv;
                    stage[idx] = nv;
                }
            } else {
                stage[idx] = __floats2half2_rn(0.f, 0.f);
            }
        }
        __syncwarp();

        wmma::fragment<wmma::matrix_a, 16,16,16, __half, wmma::row_major> a0, a1, a2, a3;
        wmma::load_matrix_sync(a0, sE[warp],            32);   // rows 0-15,  k 0-15
        wmma::load_matrix_sync(a1, sE[warp] + 16,       32);   // rows 0-15,  k 16-31
        wmma::load_matrix_sync(a2, sE[warp] + 512,      32);   // rows 16-31, k 0-15
        wmma::load_matrix_sync(a3, sE[warp] + 512 + 16, 32);   // rows 16-31, k 16-31

        wmma::fragment<wmma::accumulator, 16,16,16, float> c0, c1, c2, c3;
        wmma::fill_fragment(c0, 0.f); wmma::fill_fragment(c1, 0.f);
        wmma::fill_fragment(c2, 0.f); wmma::fill_fragment(c3, 0.f);
        wmma::mma_sync(c0, a0, bh[0][0], c0); wmma::mma_sync(c2, a2, bh[0][0], c2);
        wmma::mma_sync(c0, a1, bh[1][0], c0); wmma::mma_sync(c2, a3, bh[1][0], c2);
        wmma::mma_sync(c0, a0, bl[0][0], c0); wmma::mma_sync(c2, a2, bl[0][0], c2);
        wmma::mma_sync(c0, a1, bl[1][0], c0); wmma::mma_sync(c2, a3, bl[1][0], c2);
        wmma::mma_sync(c1, a0, bh[0][1], c1); wmma::mma_sync(c3, a2, bh[0][1], c3);
        wmma::mma_sync(c1, a1, bh[1][1], c1); wmma::mma_sync(c3, a3, bh[1][1], c3);
        wmma::mma_sync(c1, a0, bl[0][1], c1); wmma::mma_sync(c3, a2, bl[0][1], c3);
        wmma::mma_sync(c1, a1, bl[1][1], c1); wmma::mma_sync(c3, a3, bl[1][1], c3);

        wmma::store_matrix_sync(sC[warp],             c0, 32, wmma::mem_row_major);
        wmma::store_matrix_sync(sC[warp] + 16,        c1, 32, wmma::mem_row_major);
        wmma::store_matrix_sync(sC[warp] + 512,       c2, 32, wmma::mem_row_major);
        wmma::store_matrix_sync(sC[warp] + 512 + 16,  c3, 32, wmma::mem_row_major);
        __syncwarp();

        #pragma unroll
        for (int r = 0; r < 32; r++) {
            int row = rbase + r;
            if (row < ne)
                g_ce[(size_t)row*32 + lane] =
                    __float2half_rn(sC[warp][r*32 + lane] + sBias[lane]);
        }
        __syncwarp();
    }
}

// ---- aggregation: warp per node; software-pipelined ILP4 -------------------------
__global__ void agg2(int curSlot, int n)
{
    int lane = threadIdx.x & 31;

    __shared__ float sE[32], qE[32], sH[32], qH[32];
    if (threadIdx.x < 32) {
        sE[threadIdx.x] = 0.f; qE[threadIdx.x] = 0.f;
        sH[threadIdx.x] = 0.f; qH[threadIdx.x] = 0.f;
    }
    __syncthreads();

    float ls = 0.f, lq = 0.f, hs = 0.f, hq = 0.f;
    int d = blockIdx.x * (blockDim.x >> 5) + (threadIdx.x >> 5);
    if (d < n) {
        int beg = g_rowptr[d], end = g_rowptr[d+1];
        float ah = g_Ah[d*H + lane];
        float uh = g_Uh[d*H + lane];
        float num = 0.f, den = 0.f;
        int nfull = (end - beg) & ~3;
        int endf = beg + nfull;
        int i = beg;
        int   sP[4];
        float ceP[4];
        if (i < endf) {
            #pragma unroll
            for (int j = 0; j < 4; j++) sP[j] = g_ssrc[i+j];
            #pragma unroll
            for (int j = 0; j < 4; j++) ceP[j] = __half2float(g_ce[(size_t)(i+j)*H + lane]);
        }
        for (; i < endf; i += 4) {
            int   sc_[4];
            float cec[4];
            #pragma unroll
            for (int j = 0; j < 4; j++) { sc_[j] = sP[j]; cec[j] = ceP[j]; }
            int inext = i + 4;
            if (inext < endf) {          // prefetch next group (independent loads)
                #pragma unroll
                for (int j = 0; j < 4; j++) sP[j] = g_ssrc[inext+j];
                #pragma unroll
                for (int j = 0; j < 4; j++)
                    ceP[j] = __half2float(g_ce[(size_t)(inext+j)*H + lane]);
            }
            float bh[4], vh[4];
            #pragma unroll
            for (int j = 0; j < 4; j++) bh[j] = g_Bh[sc_[j]*H + lane];
            #pragma unroll
            for (int j = 0; j < 4; j++) vh[j] = g_Vh[sc_[j]*H + lane];
            #pragma unroll
            for (int j = 0; j < 4; j++) {
                float en = ah + bh[j] + cec[j];
                ls += en; lq += en * en;
                float sg = 1.0f / (1.0f + __expf(-en));
                num += sg * vh[j];
                den += sg;
            }
        }
        for (; i < end; i++) {
            int s0 = g_ssrc[i];
            float en = ah + g_Bh[s0*H + lane] + __half2float(g_ce[(size_t)i*H + lane]);
            ls += en; lq += en * en;
            float sg0 = 1.0f / (1.0f + __expf(-en));
            num += sg0 * g_Vh[s0*H + lane];
            den += sg0;
        }
        float hn = uh + num / (den + 1e-6f);
        g_hnew[d*H + lane] = hn;
        hs += hn; hq += hn * hn;
    }
    atomicAdd(&sH[lane], hs); atomicAdd(&qH[lane], hq);
    atomicAdd(&sE[lane], ls); atomicAdd(&qE[lane], lq);
    __syncthreads();
    if (threadIdx.x < 32) {
        atomicAdd(&g_stats[curSlot*128 + threadIdx.x],      sH[threadIdx.x]);
        atomicAdd(&g_stats[curSlot*128 + 32 + threadIdx.x], qH[threadIdx.x]);
        atomicAdd(&g_stats[curSlot*128 + 64 + threadIdx.x], sE[threadIdx.x]);
        atomicAdd(&g_stats[curSlot*128 + 96 + threadIdx.x], qE[threadIdx.x]);
    }
}

// ---- score pre-pass: final h-update fused; hid_src -> g_Ah, hid_dst -> g_Bh ------
__global__ void __launch_bounds__(128)
score_gemm2(const float* __restrict__ W1, const float* __restrict__ b1,
            const float* __restrict__ bng, const float* __restrict__ bnb,
            int statSlot, int n)
{
    int lane = threadIdx.x & 31;
    float ws[32], wd[32];
    #pragma unroll
    for (int k = 0; k < 32; k++) {
        ws[k] = W1[k*32 + lane];
        wd[k] = W1[(32 + k)*32 + lane];
    }
    float bb = b1[lane];
    float inv = 1.0f / (float)n;
    float s1 = g_stats[statSlot*128 + lane];
    float s2 = g_stats[statSlot*128 + 32 + lane];
    float mn = s1 * inv;
    float var = s2 * inv - mn * mn;
    float sc = rsqrtf(var + 1e-5f) * bng[lane];
    float bt = bnb[lane];

    int warp0  = blockIdx.x * (blockDim.x >> 5) + (threadIdx.x >> 5);
    int stride = gridDim.x * (blockDim.x >> 5);
    for (int row = warp0; row < n; row += stride) {
        float hv = g_h[row*H + lane];
        hv += fmaxf((g_hnew[row*H + lane] - mn) * sc + bt, 0.f);
        float a = bb, c = 0.f;
        #pragma unroll
        for (int k = 0; k < 32; k++) {
            float hk = __shfl_sync(FULL, hv, k);
            a += hk * ws[k];
            c += hk * wd[k];
        }
        g_Ah[row*H + lane] = a;
        g_Bh[row*H + lane] = c;
    }
}

// ---- score: 2 edges per warp; hid = relu(sum); out = hid @ W2 + b2 ---------------
__global__ void score_final(const float* __restrict__ W2, const float* __restrict__ b2,
                            float* __restrict__ out, int ne)
{
    int lane = threadIdx.x & 31;
    float w2 = W2[lane];
    float bb2 = b2[0];

    int w  = blockIdx.x * (blockDim.x >> 5) + (threadIdx.x >> 5);
    int i0 = w*2, i1 = w*2 + 1;
    if (i0 >= ne) return;

    int s0 = g_ssrc[i0], d0 = g_sdst[i0], o0 = g_oid[i0];
    float h0 = g_Ah[s0*H + lane] + g_Bh[d0*H + lane]
             + __half2float(g_ce[(size_t)i0*H + lane]);
    bool has1 = (i1 < ne);
    float h1 = 0.f; int o1 = 0;
    if (has1) {
        int s1 = g_ssrc[i1], d1 = g_sdst[i1];
        o1 = g_oid[i1];
        h1 = g_Ah[s1*H + lane] + g_Bh[d1*H + lane]
           + __half2float(g_ce[(size_t)i1*H + lane]);
    }
    float p0 = fmaxf(h0, 0.f) * w2;
    float p1 = fmaxf(h1, 0.f) * w2;
    #pragma unroll
    for (int off = 16; off > 0; off >>= 1) {
        p0 += __shfl_xor_sync(FULL, p0, off);
        p1 += __shfl_xor_sync(FULL, p1, off);
    }
    if (lane == 0) {
        out[o0] = p0 + bb2;
        if (has1) out[o1] = p1 + bb2;
    }
}

// ==================================================================================
extern "C" void kernel_launch(void* const* d_in, const int* in_sizes, int n_in,
                              void* d_out, int out_size)
{
    const float* x    = (const float*)d_in[0];
    const float* ein  = (const float*)d_in[1];
    const int*   eidx = (const int*)  d_in[2];
    const float* pe_w = (const float*)d_in[3];
    const float* pe_b = (const float*)d_in[4];
    const float* ed_w = (const float*)d_in[5];
    const float* ed_b = (const float*)d_in[6];
    const float* A_w  = (const float*)d_in[7];
    const float* A_b  = (const float*)d_in[8];
    const float* B_w  = (const float*)d_in[9];
    const float* B_b  = (const float*)d_in[10];
    const float* C_w  = (const float*)d_in[11];
    const float* C_b  = (const float*)d_in[12];
    const float* U_w  = (const float*)d_in[13];
    const float* U_b  = (const float*)d_in[14];
    const float* V_w  = (const float*)d_in[15];
    const float* V_b  = (const float*)d_in[16];
    const float* bnhg = (const float*)d_in[17];
    const float* bnhb = (const float*)d_in[18];
    const float* bneg = (const float*)d_in[19];
    const float* bneb = (const float*)d_in[20];
    const float* W1_w = (const float*)d_in[21];
    const float* W1_b = (const float*)d_in[22];
    const float* W2_w = (const float*)d_in[23];
    const float* W2_b = (const float*)d_in[24];
    float* out = (float*)d_out;

    const int n  = in_sizes[0];
    const int ne = in_sizes[1];
    const int* src = eidx;
    const int* dst = eidx + ne;
    const float inv_ne = 1.0f / (float)ne;

    const int TB = 256;
    const int WPB = TB / 32;
    const int G_NODE_W  = (n + WPB - 1) / WPB;
    const int G_SCORE   = ((ne + 1)/2 + WPB - 1) / WPB;   // 2 edges per warp
    const int G_MMA  = 1480;
    const int G_G4   = 1480;

    // ---- CSR build ----
    hist_kernel<<<800, TB>>>(dst, ne);                 // #1
    scan_fused<<<SCAN_NB, 1024>>>();                   // #2
    scatter_kernel<<<800, TB>>>(src, dst, ne);         // #3

    for (int l = 0; l < NL; l++) {
        // ce_mma BEFORE gemm4: eMode 2 reconstructs enew_{l-1} from old Ah/Bh.
        ce_mma<<<G_MMA, 128>>>(C_w + l*H*H, C_b + l*H,          // #4 = ce_mma(l0)
                               bneg + (l-1)*H, bneb + (l-1)*H,
                               ein, ed_w, ed_b,
                               l-1, l == 0 ? 1 : 2, /*writeE=*/1, ne, inv_ne);

        gemm4_fused<<<G_G4, 128>>>(A_w + l*H*H, A_b + l*H,
                                   B_w + l*H*H, B_b + l*H,
                                   U_w + l*H*H, U_b + l*H,
                                   V_w + l*H*H, V_b + l*H,
                                   bnhg + (l-1)*H, bnhb + (l-1)*H,
                                   x, pe_w, pe_b,
                                   l-1, l == 0 ? 0 : 1, n);

        agg2<<<G_NODE_W, TB>>>(l, n);
    }

    // final edge term BEFORE score_gemm2 (needs Ah_3/Bh_3 for enew reconstruction)
    ce_mma<<<G_MMA, 128>>>(W1_w + 64*32, (const float*)nullptr,
                           bneg + (NL-1)*H, bneb + (NL-1)*H,
                           (const float*)nullptr, (const float*)nullptr,
                           (const float*)nullptr,
                           NL-1, /*eMode=*/2, /*writeE=*/0, ne, inv_ne);
    score_gemm2<<<G_G4, 128>>>(W1_w, W1_b,
                               bnhg + (NL-1)*H, bnhb + (NL-1)*H, NL-1, n);
    score_final<<<G_SCORE, TB>>>(W2_w, W2_b, out, ne);
}